// round 5
// baseline (speedup 1.0000x reference)
#include <cuda_runtime.h>
#include <cstdint>

#define BB 4
#define SS 2048
#define NH 16
#define HD 64
#define DM 1024

// Scratch for Q/K/V in [B, H, S, hd] layout (device globals: allocation-free).
__device__ __align__(16) float g_q[BB * NH * SS * HD];
__device__ __align__(16) float g_k[BB * NH * SS * HD];
__device__ __align__(16) float g_v[BB * NH * SS * HD];

__device__ __forceinline__ unsigned f2tf(float x) {
    unsigned u;
    asm("cvt.rna.tf32.f32 %0, %1;" : "=r"(u) : "f"(x));
    return u;
}

__device__ __forceinline__ void mma_tf32(float* c, const unsigned* a, const unsigned* b) {
    asm volatile(
        "mma.sync.aligned.m16n8k8.row.col.f32.tf32.tf32.f32 "
        "{%0,%1,%2,%3}, {%4,%5,%6,%7}, {%8,%9}, {%0,%1,%2,%3};"
        : "+f"(c[0]), "+f"(c[1]), "+f"(c[2]), "+f"(c[3])
        : "r"(a[0]), "r"(a[1]), "r"(a[2]), "r"(a[3]), "r"(b[0]), "r"(b[1]));
}

// ---------------------------------------------------------------------------
// Kernel 1: fused QKV projection with tf32 mma.sync (unchanged from R3).
// ---------------------------------------------------------------------------
__global__ __launch_bounds__(256) void qkv_kernel(
    const float* __restrict__ x,
    const float* __restrict__ Wq, const float* __restrict__ bq,
    const float* __restrict__ Wk, const float* __restrict__ bk,
    const float* __restrict__ Wv, const float* __restrict__ bv)
{
    __shared__ unsigned As[128 * 36];
    __shared__ unsigned Bs[64 * 36];

    const int tid = threadIdx.x;
    const int lane = tid & 31;
    const int w = tid >> 5;
    const int wm = w & 3;
    const int wn = w >> 2;
    const int mRow0 = wm * 32;
    const int nCol0 = wn * 32;

    const int rowBase = blockIdx.y * 128;
    const int colBase = blockIdx.x * 64;
    const int mat = colBase / DM;
    const int colInMat = colBase % DM;
    const int head = colInMat / HD;

    const float* W    = (mat == 0) ? Wq : (mat == 1) ? Wk : Wv;
    const float* bias = (mat == 0) ? bq : (mat == 1) ? bk : bv;
    float*       dst  = (mat == 0) ? g_q : (mat == 1) ? g_k : g_v;

    float acc[2][4][4] = {};

    for (int kt = 0; kt < DM; kt += 32) {
        #pragma unroll
        for (int j = 0; j < 4; j++) {
            int idx = tid + j * 256;
            int row = idx >> 3;
            int c4 = (idx & 7) * 4;
            float4 a = *(const float4*)&x[(size_t)(rowBase + row) * DM + kt + c4];
            unsigned* p = &As[row * 36 + c4];
            p[0] = f2tf(a.x); p[1] = f2tf(a.y); p[2] = f2tf(a.z); p[3] = f2tf(a.w);
        }
        #pragma unroll
        for (int j = 0; j < 2; j++) {
            int idx = tid + j * 256;
            int row = idx >> 3;
            int c4 = (idx & 7) * 4;
            float4 bvv = *(const float4*)&W[(size_t)(colInMat + row) * DM + kt + c4];
            unsigned* p = &Bs[row * 36 + c4];
            p[0] = f2tf(bvv.x); p[1] = f2tf(bvv.y); p[2] = f2tf(bvv.z); p[3] = f2tf(bvv.w);
        }
        __syncthreads();

        #pragma unroll
        for (int kk = 0; kk < 4; kk++) {
            const int col = kk * 8 + (lane & 3);
            unsigned a[2][4];
            #pragma unroll
            for (int mi = 0; mi < 2; mi++) {
                int r = mRow0 + mi * 16 + (lane >> 2);
                a[mi][0] = As[r * 36 + col];
                a[mi][1] = As[(r + 8) * 36 + col];
                a[mi][2] = As[r * 36 + col + 4];
                a[mi][3] = As[(r + 8) * 36 + col + 4];
            }
            #pragma unroll
            for (int ni = 0; ni < 4; ni++) {
                int n0 = nCol0 + ni * 8 + (lane >> 2);
                unsigned b[2];
                b[0] = Bs[n0 * 36 + col];
                b[1] = Bs[n0 * 36 + col + 4];
                mma_tf32(acc[0][ni], a[0], b);
                mma_tf32(acc[1][ni], a[1], b);
            }
        }
        __syncthreads();
    }

    #pragma unroll
    for (int mi = 0; mi < 2; mi++) {
        #pragma unroll
        for (int ni = 0; ni < 4; ni++) {
            int d = nCol0 + ni * 8 + 2 * (lane & 3);
            float b0 = bias[colInMat + d];
            float b1 = bias[colInMat + d + 1];
            #pragma unroll
            for (int half = 0; half < 2; half++) {
                int token = rowBase + mRow0 + mi * 16 + (lane >> 2) + half * 8;
                int bidx = token >> 11;
                int s = token & (SS - 1);
                float2 o;
                o.x = acc[mi][ni][half * 2 + 0] + b0;
                o.y = acc[mi][ni][half * 2 + 1] + b1;
                *(float2*)&dst[(((size_t)(bidx * NH + head)) * SS + s) * HD + d] = o;
            }
        }
    }
}

// ---------------------------------------------------------------------------
// Kernel 2: attention, tf32 MMA, register-resident P via intra-warp shuffle.
// Block: one (b,h), 64 q rows, 4 warps; warp = 16 q x full 64-key tile.
// S accumulators are converted to PV A-operands with shfl (no P smem).
// K buffer: natural [key][d], stride 68 (scalar B reads bank-perfect,
//   STS.128 stores conflict-free). V buffer: natural [key][d], stride 72.
// Double-buffered -> one __syncthreads per tile.
// ---------------------------------------------------------------------------
#define KSTR 68
#define VSTR 72
#define KWORDS (64 * KSTR)          // 4352
#define VWORDS (64 * VSTR)          // 4608
#define ATTN_SMEM_BYTES ((2 * KWORDS + 2 * VWORDS) * 4)   // 71680

__global__ __launch_bounds__(128) void attn_kernel(
    const float* __restrict__ mask, float* __restrict__ out)
{
    extern __shared__ unsigned smem[];
    unsigned* kbuf[2] = { smem, smem + KWORDS };
    unsigned* vbuf[2] = { smem + 2 * KWORDS, smem + 2 * KWORDS + VWORDS };

    const int tid = threadIdx.x;
    const int lane = tid & 31;
    const int w = tid >> 5;
    const int qRow0 = w * 16;
    const int t = lane & 3;
    const int g = lane >> 2;

    const int bh = blockIdx.y;
    const int b = bh >> 4;
    const int h = bh & 15;
    const int qBase = blockIdx.x * 64;

    const float* qg = g_q + (size_t)bh * SS * HD;
    const float* kg = g_k + (size_t)bh * SS * HD;
    const float* vg = g_v + (size_t)bh * SS * HD;
    const float* maskrow = mask + b * SS;

    const float scale = 0.125f;

    // Shuffle sources for accumulator->A-operand layout conversion.
    const int src1 = (lane & ~3) | (t >> 1);
    const int src2 = src1 + 2;
    const bool odd = (t & 1) != 0;

    // Hoist Q fragments (all 8 k-steps of d).
    unsigned a_q[8][4];
    {
        int r0 = qBase + qRow0 + g;
        int r1 = r0 + 8;
        #pragma unroll
        for (int kk = 0; kk < 8; kk++) {
            int col = kk * 8 + t;
            a_q[kk][0] = f2tf(qg[(size_t)r0 * HD + col]);
            a_q[kk][1] = f2tf(qg[(size_t)r1 * HD + col]);
            a_q[kk][2] = f2tf(qg[(size_t)r0 * HD + col + 4]);
            a_q[kk][3] = f2tf(qg[(size_t)r1 * HD + col + 4]);
        }
    }

    // Tile loaders: 64 keys x 64 dims, 128 threads, 8 float4 each.
    const int lrow = tid >> 4;            // 0..7 (+8j)
    const int lc4 = (tid & 15) * 4;       // 0..60

    float ctx[8][4] = {};

    // Preload tile 0.
    {
        #pragma unroll
        for (int j = 0; j < 8; j++) {
            int row = lrow + j * 8;
            float4 kv = *(const float4*)&kg[(size_t)row * HD + lc4];
            uint4 ku;
            ku.x = f2tf(kv.x); ku.y = f2tf(kv.y); ku.z = f2tf(kv.z); ku.w = f2tf(kv.w);
            *(uint4*)&kbuf[0][row * KSTR + lc4] = ku;
            float4 vv = *(const float4*)&vg[(size_t)row * HD + lc4];
            uint4 vu;
            vu.x = f2tf(vv.x); vu.y = f2tf(vv.y); vu.z = f2tf(vv.z); vu.w = f2tf(vv.w);
            *(uint4*)&vbuf[0][row * VSTR + lc4] = vu;
        }
    }
    __syncthreads();

    for (int tt = 0; tt < 32; tt++) {
        const unsigned* kc = kbuf[tt & 1];
        const unsigned* vc = vbuf[tt & 1];
        unsigned* kn = kbuf[(tt + 1) & 1];
        unsigned* vn = vbuf[(tt + 1) & 1];
        const bool pf = (tt < 31);

        // Prefetch next K tile into registers (LDG issues early).
        float4 kreg[8];
        if (pf) {
            const float* kt = kg + (size_t)((tt + 1) * 64) * HD;
            #pragma unroll
            for (int j = 0; j < 8; j++)
                kreg[j] = *(const float4*)&kt[(size_t)(lrow + j * 8) * HD + lc4];
        }

        // --- S = Q K^T : warp covers 16 q x 64 keys ---
        float s[8][4] = {};
        #pragma unroll
        for (int kk = 0; kk < 8; kk++) {
            #pragma unroll
            for (int ni = 0; ni < 8; ni++) {
                const unsigned* kr = &kc[(ni * 8 + g) * KSTR + kk * 8 + t];
                unsigned bf[2] = { kr[0], kr[4] };
                mma_tf32(s[ni], a_q[kk], bf);
            }
        }

        // Store prefetched K; prefetch V.
        float4 vreg[8];
        if (pf) {
            #pragma unroll
            for (int j = 0; j < 8; j++) {
                uint4 ku;
                ku.x = f2tf(kreg[j].x); ku.y = f2tf(kreg[j].y);
                ku.z = f2tf(kreg[j].z); ku.w = f2tf(kreg[j].w);
                *(uint4*)&kn[(lrow + j * 8) * KSTR + lc4] = ku;
            }
            const float* vt = vg + (size_t)((tt + 1) * 64) * HD;
            #pragma unroll
            for (int j = 0; j < 8; j++)
                vreg[j] = *(const float4*)&vt[(size_t)(lrow + j * 8) * HD + lc4];
        }

        // --- P = relu(S*scale + mask)^2 in regs; shuffle to A-operand layout ---
        unsigned pa[8][4];
        #pragma unroll
        for (int ni = 0; ni < 8; ni++) {
            float2 m2 = *(const float2*)&maskrow[tt * 64 + ni * 8 + 2 * t];
            float p0 = fmaxf(s[ni][0] * scale + m2.x, 0.0f);
            float p1 = fmaxf(s[ni][1] * scale + m2.y, 0.0f);
            float p2 = fmaxf(s[ni][2] * scale + m2.x, 0.0f);
            float p3 = fmaxf(s[ni][3] * scale + m2.y, 0.0f);
            unsigned u0 = f2tf(p0 * p0);
            unsigned u1 = f2tf(p1 * p1);
            unsigned u2 = f2tf(p2 * p2);
            unsigned u3 = f2tf(p3 * p3);
            unsigned x0 = __shfl_sync(0xffffffffu, u0, src1);
            unsigned x1 = __shfl_sync(0xffffffffu, u1, src1);
            unsigned z0 = __shfl_sync(0xffffffffu, u2, src1);
            unsigned z1 = __shfl_sync(0xffffffffu, u3, src1);
            unsigned y0 = __shfl_sync(0xffffffffu, u0, src2);
            unsigned y1 = __shfl_sync(0xffffffffu, u1, src2);
            unsigned w0 = __shfl_sync(0xffffffffu, u2, src2);
            unsigned w1 = __shfl_sync(0xffffffffu, u3, src2);
            pa[ni][0] = odd ? x1 : x0;
            pa[ni][1] = odd ? z1 : z0;
            pa[ni][2] = odd ? y1 : y0;
            pa[ni][3] = odd ? w1 : w0;
        }

        // --- ctx += P @ V : warp covers 16 q x 64 dims ---
        #pragma unroll
        for (int kk = 0; kk < 8; kk++) {
            #pragma unroll
            for (int ti = 0; ti < 8; ti++) {
                unsigned bf[2];
                bf[0] = vc[(kk * 8 + t) * VSTR + ti * 8 + g];
                bf[1] = vc[(kk * 8 + t + 4) * VSTR + ti * 8 + g];
                mma_tf32(ctx[ti], pa[kk], bf);
            }
        }

        // Store prefetched V.
        if (pf) {
            #pragma unroll
            for (int j = 0; j < 8; j++) {
                uint4 vu;
                vu.x = f2tf(vreg[j].x); vu.y = f2tf(vreg[j].y);
                vu.z = f2tf(vreg[j].z); vu.w = f2tf(vreg[j].w);
                *(uint4*)&vn[(lrow + j * 8) * VSTR + lc4] = vu;
            }
        }
        __syncthreads();
    }

    // Write context: out[b][s][h*64 + d].
    {
        int r0 = qBase + qRow0 + g;
        float* o0 = out + ((size_t)(b * SS + r0)) * DM + h * HD;
        float* o1 = o0 + (size_t)8 * DM;
        #pragma unroll
        for (int ti = 0; ti < 8; ti++) {
            int d = ti * 8 + 2 * t;
            *(float2*)&o0[d] = make_float2(ctx[ti][0], ctx[ti][1]);
            *(float2*)&o1[d] = make_float2(ctx[ti][2], ctx[ti][3]);
        }
    }
}

extern "C" void kernel_launch(void* const* d_in, const int* in_sizes, int n_in,
                              void* d_out, int out_size)
{
    const float* x    = (const float*)d_in[0];
    const float* mask = (const float*)d_in[1];
    const float* Wq   = (const float*)d_in[2];
    const float* bq   = (const float*)d_in[3];
    const float* Wk   = (const float*)d_in[4];
    const float* bk   = (const float*)d_in[5];
    const float* Wv   = (const float*)d_in[6];
    const float* bv   = (const float*)d_in[7];
    float* out = (float*)d_out;

    cudaFuncSetAttribute(attn_kernel,
                         cudaFuncAttributeMaxDynamicSharedMemorySize,
                         ATTN_SMEM_BYTES);

    qkv_kernel<<<dim3(3 * DM / 64, (BB * SS) / 128), 256>>>(
        x, Wq, bq, Wk, bk, Wv, bv);

    attn_kernel<<<dim3(SS / 64, BB * NH), 128, ATTN_SMEM_BYTES>>>(mask, out);
}

// round 6
// speedup vs baseline: 1.0419x; 1.0419x over previous
#include <cuda_runtime.h>
#include <cstdint>

#define BB 4
#define SS 2048
#define NH 16
#define HD 64
#define DM 1024

// Scratch for Q/K/V in [B, H, S, hd] layout (device globals: allocation-free).
__device__ __align__(16) float g_q[BB * NH * SS * HD];
__device__ __align__(16) float g_k[BB * NH * SS * HD];
__device__ __align__(16) float g_v[BB * NH * SS * HD];

__device__ __forceinline__ unsigned f2tf(float x) {
    unsigned u;
    asm("cvt.rna.tf32.f32 %0, %1;" : "=r"(u) : "f"(x));
    return u;
}

__device__ __forceinline__ void mma_tf32(float* c, const unsigned* a, const unsigned* b) {
    asm volatile(
        "mma.sync.aligned.m16n8k8.row.col.f32.tf32.tf32.f32 "
        "{%0,%1,%2,%3}, {%4,%5,%6,%7}, {%8,%9}, {%0,%1,%2,%3};"
        : "+f"(c[0]), "+f"(c[1]), "+f"(c[2]), "+f"(c[3])
        : "r"(a[0]), "r"(a[1]), "r"(a[2]), "r"(a[3]), "r"(b[0]), "r"(b[1]));
}

// ---------------------------------------------------------------------------
// Kernel 1: fused QKV projection with tf32 mma.sync (unchanged from R3).
// ---------------------------------------------------------------------------
__global__ __launch_bounds__(256) void qkv_kernel(
    const float* __restrict__ x,
    const float* __restrict__ Wq, const float* __restrict__ bq,
    const float* __restrict__ Wk, const float* __restrict__ bk,
    const float* __restrict__ Wv, const float* __restrict__ bv)
{
    __shared__ unsigned As[128 * 36];
    __shared__ unsigned Bs[64 * 36];

    const int tid = threadIdx.x;
    const int lane = tid & 31;
    const int w = tid >> 5;
    const int wm = w & 3;
    const int wn = w >> 2;
    const int mRow0 = wm * 32;
    const int nCol0 = wn * 32;

    const int rowBase = blockIdx.y * 128;
    const int colBase = blockIdx.x * 64;
    const int mat = colBase / DM;
    const int colInMat = colBase % DM;
    const int head = colInMat / HD;

    const float* W    = (mat == 0) ? Wq : (mat == 1) ? Wk : Wv;
    const float* bias = (mat == 0) ? bq : (mat == 1) ? bk : bv;
    float*       dst  = (mat == 0) ? g_q : (mat == 1) ? g_k : g_v;

    float acc[2][4][4] = {};

    for (int kt = 0; kt < DM; kt += 32) {
        #pragma unroll
        for (int j = 0; j < 4; j++) {
            int idx = tid + j * 256;
            int row = idx >> 3;
            int c4 = (idx & 7) * 4;
            float4 a = *(const float4*)&x[(size_t)(rowBase + row) * DM + kt + c4];
            unsigned* p = &As[row * 36 + c4];
            p[0] = f2tf(a.x); p[1] = f2tf(a.y); p[2] = f2tf(a.z); p[3] = f2tf(a.w);
        }
        #pragma unroll
        for (int j = 0; j < 2; j++) {
            int idx = tid + j * 256;
            int row = idx >> 3;
            int c4 = (idx & 7) * 4;
            float4 bvv = *(const float4*)&W[(size_t)(colInMat + row) * DM + kt + c4];
            unsigned* p = &Bs[row * 36 + c4];
            p[0] = f2tf(bvv.x); p[1] = f2tf(bvv.y); p[2] = f2tf(bvv.z); p[3] = f2tf(bvv.w);
        }
        __syncthreads();

        #pragma unroll
        for (int kk = 0; kk < 4; kk++) {
            const int col = kk * 8 + (lane & 3);
            unsigned a[2][4];
            #pragma unroll
            for (int mi = 0; mi < 2; mi++) {
                int r = mRow0 + mi * 16 + (lane >> 2);
                a[mi][0] = As[r * 36 + col];
                a[mi][1] = As[(r + 8) * 36 + col];
                a[mi][2] = As[r * 36 + col + 4];
                a[mi][3] = As[(r + 8) * 36 + col + 4];
            }
            #pragma unroll
            for (int ni = 0; ni < 4; ni++) {
                int n0 = nCol0 + ni * 8 + (lane >> 2);
                unsigned b[2];
                b[0] = Bs[n0 * 36 + col];
                b[1] = Bs[n0 * 36 + col + 4];
                mma_tf32(acc[0][ni], a[0], b);
                mma_tf32(acc[1][ni], a[1], b);
            }
        }
        __syncthreads();
    }

    #pragma unroll
    for (int mi = 0; mi < 2; mi++) {
        #pragma unroll
        for (int ni = 0; ni < 4; ni++) {
            int d = nCol0 + ni * 8 + 2 * (lane & 3);
            float b0 = bias[colInMat + d];
            float b1 = bias[colInMat + d + 1];
            #pragma unroll
            for (int half = 0; half < 2; half++) {
                int token = rowBase + mRow0 + mi * 16 + (lane >> 2) + half * 8;
                int bidx = token >> 11;
                int s = token & (SS - 1);
                float2 o;
                o.x = acc[mi][ni][half * 2 + 0] + b0;
                o.y = acc[mi][ni][half * 2 + 1] + b1;
                *(float2*)&dst[(((size_t)(bidx * NH + head)) * SS + s) * HD + d] = o;
            }
        }
    }
}

// ---------------------------------------------------------------------------
// Kernel 2: attention, tf32 MMA, register-resident P, split 32-key halves.
// Block: one (b,h), 64 q rows, 4 warps; warp = 16 q x full 64-key tile.
// Per tile: [LDG next K] S0(keys0-31) pa0 PV0 | [STS K, LDG next V]
//           S1(keys32-63) pa1 PV1 | [STS V] sync.
// Staging registers (32) have disjoint live ranges across the two halves;
// s/pa are 16+16 regs peak. launch_bounds(128,3) -> >=3 CTAs/SM.
// ---------------------------------------------------------------------------
#define KSTR 68
#define VSTR 72
#define KWORDS (64 * KSTR)          // 4352
#define VWORDS (64 * VSTR)          // 4608
#define ATTN_SMEM_BYTES ((2 * KWORDS + 2 * VWORDS) * 4)   // 71680

__global__ __launch_bounds__(128, 3) void attn_kernel(
    const float* __restrict__ mask, float* __restrict__ out)
{
    extern __shared__ unsigned smem[];
    unsigned* kbuf[2] = { smem, smem + KWORDS };
    unsigned* vbuf[2] = { smem + 2 * KWORDS, smem + 2 * KWORDS + VWORDS };

    const int tid = threadIdx.x;
    const int lane = tid & 31;
    const int w = tid >> 5;
    const int qRow0 = w * 16;
    const int t = lane & 3;
    const int g = lane >> 2;

    const int bh = blockIdx.y;
    const int b = bh >> 4;
    const int h = bh & 15;
    const int qBase = blockIdx.x * 64;

    const float* qg = g_q + (size_t)bh * SS * HD;
    const float* kg = g_k + (size_t)bh * SS * HD;
    const float* vg = g_v + (size_t)bh * SS * HD;
    const float* maskrow = mask + b * SS;

    const float scale = 0.125f;

    // Shuffle sources for accumulator->A-operand layout conversion.
    const int src1 = (lane & ~3) | (t >> 1);
    const int src2 = src1 + 2;
    const bool odd = (t & 1) != 0;

    // Hoist Q fragments (all 8 k-steps of d).
    unsigned a_q[8][4];
    {
        int r0 = qBase + qRow0 + g;
        int r1 = r0 + 8;
        #pragma unroll
        for (int kk = 0; kk < 8; kk++) {
            int col = kk * 8 + t;
            a_q[kk][0] = f2tf(qg[(size_t)r0 * HD + col]);
            a_q[kk][1] = f2tf(qg[(size_t)r1 * HD + col]);
            a_q[kk][2] = f2tf(qg[(size_t)r0 * HD + col + 4]);
            a_q[kk][3] = f2tf(qg[(size_t)r1 * HD + col + 4]);
        }
    }

    // Tile loaders: 64 keys x 64 dims, 128 threads, 8 float4 each.
    const int lrow = tid >> 4;            // 0..7 (+8j)
    const int lc4 = (tid & 15) * 4;       // 0..60

    float ctx[8][4] = {};

    // Preload tile 0.
    #pragma unroll
    for (int j = 0; j < 8; j++) {
        int row = lrow + j * 8;
        float4 kv = *(const float4*)&kg[(size_t)row * HD + lc4];
        uint4 ku;
        ku.x = f2tf(kv.x); ku.y = f2tf(kv.y); ku.z = f2tf(kv.z); ku.w = f2tf(kv.w);
        *(uint4*)&kbuf[0][row * KSTR + lc4] = ku;
        float4 vv = *(const float4*)&vg[(size_t)row * HD + lc4];
        uint4 vu;
        vu.x = f2tf(vv.x); vu.y = f2tf(vv.y); vu.z = f2tf(vv.z); vu.w = f2tf(vv.w);
        *(uint4*)&vbuf[0][row * VSTR + lc4] = vu;
    }
    __syncthreads();

    for (int tt = 0; tt < 32; tt++) {
        const unsigned* kc = kbuf[tt & 1];
        const unsigned* vc = vbuf[tt & 1];
        unsigned* kn = kbuf[(tt + 1) & 1];
        unsigned* vn = vbuf[(tt + 1) & 1];
        const bool pf = (tt < 31);

        // ---- HALF 0 : keys 0..31 ----
        // Prefetch next K tile into registers (live through half 0 only).
        float4 stg[8];
        if (pf) {
            const float* kt = kg + (size_t)((tt + 1) * 64) * HD;
            #pragma unroll
            for (int j = 0; j < 8; j++)
                stg[j] = *(const float4*)&kt[(size_t)(lrow + j * 8) * HD + lc4];
        }

        {
            float s[4][4] = {};
            #pragma unroll
            for (int kk = 0; kk < 8; kk++) {
                #pragma unroll
                for (int ni = 0; ni < 4; ni++) {
                    const unsigned* kr = &kc[(ni * 8 + g) * KSTR + kk * 8 + t];
                    unsigned bf[2] = { kr[0], kr[4] };
                    mma_tf32(s[ni], a_q[kk], bf);
                }
            }
            unsigned pa[4][4];
            #pragma unroll
            for (int ni = 0; ni < 4; ni++) {
                float2 m2 = *(const float2*)&maskrow[tt * 64 + ni * 8 + 2 * t];
                float p0 = fmaxf(s[ni][0] * scale + m2.x, 0.0f);
                float p1 = fmaxf(s[ni][1] * scale + m2.y, 0.0f);
                float p2 = fmaxf(s[ni][2] * scale + m2.x, 0.0f);
                float p3 = fmaxf(s[ni][3] * scale + m2.y, 0.0f);
                unsigned u0 = f2tf(p0 * p0);
                unsigned u1 = f2tf(p1 * p1);
                unsigned u2 = f2tf(p2 * p2);
                unsigned u3 = f2tf(p3 * p3);
                unsigned x0 = __shfl_sync(0xffffffffu, u0, src1);
                unsigned x1 = __shfl_sync(0xffffffffu, u1, src1);
                unsigned z0 = __shfl_sync(0xffffffffu, u2, src1);
                unsigned z1 = __shfl_sync(0xffffffffu, u3, src1);
                unsigned y0 = __shfl_sync(0xffffffffu, u0, src2);
                unsigned y1 = __shfl_sync(0xffffffffu, u1, src2);
                unsigned w0 = __shfl_sync(0xffffffffu, u2, src2);
                unsigned w1 = __shfl_sync(0xffffffffu, u3, src2);
                pa[ni][0] = odd ? x1 : x0;
                pa[ni][1] = odd ? z1 : z0;
                pa[ni][2] = odd ? y1 : y0;
                pa[ni][3] = odd ? w1 : w0;
            }
            // PV over keys 0..31 (V rows 0..31).
            #pragma unroll
            for (int kk = 0; kk < 4; kk++) {
                #pragma unroll
                for (int ti = 0; ti < 8; ti++) {
                    unsigned bf[2];
                    bf[0] = vc[(kk * 8 + t) * VSTR + ti * 8 + g];
                    bf[1] = vc[(kk * 8 + t + 4) * VSTR + ti * 8 + g];
                    mma_tf32(ctx[ti], pa[kk], bf);
                }
            }
        }

        // Retire K staging; start V staging (live through half 1 only).
        if (pf) {
            #pragma unroll
            for (int j = 0; j < 8; j++) {
                uint4 ku;
                ku.x = f2tf(stg[j].x); ku.y = f2tf(stg[j].y);
                ku.z = f2tf(stg[j].z); ku.w = f2tf(stg[j].w);
                *(uint4*)&kn[(lrow + j * 8) * KSTR + lc4] = ku;
            }
            const float* vt = vg + (size_t)((tt + 1) * 64) * HD;
            #pragma unroll
            for (int j = 0; j < 8; j++)
                stg[j] = *(const float4*)&vt[(size_t)(lrow + j * 8) * HD + lc4];
        }

        // ---- HALF 1 : keys 32..63 ----
        {
            float s[4][4] = {};
            #pragma unroll
            for (int kk = 0; kk < 8; kk++) {
                #pragma unroll
                for (int ni = 0; ni < 4; ni++) {
                    const unsigned* kr = &kc[((ni + 4) * 8 + g) * KSTR + kk * 8 + t];
                    unsigned bf[2] = { kr[0], kr[4] };
                    mma_tf32(s[ni], a_q[kk], bf);
                }
            }
            unsigned pa[4][4];
            #pragma unroll
            for (int ni = 0; ni < 4; ni++) {
                float2 m2 = *(const float2*)&maskrow[tt * 64 + 32 + ni * 8 + 2 * t];
                float p0 = fmaxf(s[ni][0] * scale + m2.x, 0.0f);
                float p1 = fmaxf(s[ni][1] * scale + m2.y, 0.0f);
                float p2 = fmaxf(s[ni][2] * scale + m2.x, 0.0f);
                float p3 = fmaxf(s[ni][3] * scale + m2.y, 0.0f);
                unsigned u0 = f2tf(p0 * p0);
                unsigned u1 = f2tf(p1 * p1);
                unsigned u2 = f2tf(p2 * p2);
                unsigned u3 = f2tf(p3 * p3);
                unsigned x0 = __shfl_sync(0xffffffffu, u0, src1);
                unsigned x1 = __shfl_sync(0xffffffffu, u1, src1);
                unsigned z0 = __shfl_sync(0xffffffffu, u2, src1);
                unsigned z1 = __shfl_sync(0xffffffffu, u3, src1);
                unsigned y0 = __shfl_sync(0xffffffffu, u0, src2);
                unsigned y1 = __shfl_sync(0xffffffffu, u1, src2);
                unsigned w0 = __shfl_sync(0xffffffffu, u2, src2);
                unsigned w1 = __shfl_sync(0xffffffffu, u3, src2);
                pa[ni][0] = odd ? x1 : x0;
                pa[ni][1] = odd ? z1 : z0;
                pa[ni][2] = odd ? y1 : y0;
                pa[ni][3] = odd ? w1 : w0;
            }
            // PV over keys 32..63 (V rows 32..63).
            #pragma unroll
            for (int kk = 0; kk < 4; kk++) {
                #pragma unroll
                for (int ti = 0; ti < 8; ti++) {
                    unsigned bf[2];
                    bf[0] = vc[((kk + 4) * 8 + t) * VSTR + ti * 8 + g];
                    bf[1] = vc[((kk + 4) * 8 + t + 4) * VSTR + ti * 8 + g];
                    mma_tf32(ctx[ti], pa[kk], bf);
                }
            }
        }

        // Retire V staging.
        if (pf) {
            #pragma unroll
            for (int j = 0; j < 8; j++) {
                uint4 vu;
                vu.x = f2tf(stg[j].x); vu.y = f2tf(stg[j].y);
                vu.z = f2tf(stg[j].z); vu.w = f2tf(stg[j].w);
                *(uint4*)&vn[(lrow + j * 8) * VSTR + lc4] = vu;
            }
        }
        __syncthreads();
    }

    // Write context: out[b][s][h*64 + d].
    {
        int r0 = qBase + qRow0 + g;
        float* o0 = out + ((size_t)(b * SS + r0)) * DM + h * HD;
        float* o1 = o0 + (size_t)8 * DM;
        #pragma unroll
        for (int ti = 0; ti < 8; ti++) {
            int d = ti * 8 + 2 * t;
            *(float2*)&o0[d] = make_float2(ctx[ti][0], ctx[ti][1]);
            *(float2*)&o1[d] = make_float2(ctx[ti][2], ctx[ti][3]);
        }
    }
}

extern "C" void kernel_launch(void* const* d_in, const int* in_sizes, int n_in,
                              void* d_out, int out_size)
{
    const float* x    = (const float*)d_in[0];
    const float* mask = (const float*)d_in[1];
    const float* Wq   = (const float*)d_in[2];
    const float* bq   = (const float*)d_in[3];
    const float* Wk   = (const float*)d_in[4];
    const float* bk   = (const float*)d_in[5];
    const float* Wv   = (const float*)d_in[6];
    const float* bv   = (const float*)d_in[7];
    float* out = (float*)d_out;

    cudaFuncSetAttribute(attn_kernel,
                         cudaFuncAttributeMaxDynamicSharedMemorySize,
                         ATTN_SMEM_BYTES);

    qkv_kernel<<<dim3(3 * DM / 64, (BB * SS) / 128), 256>>>(
        x, Wq, bq, Wk, bk, Wv, bv);

    attn_kernel<<<dim3(SS / 64, BB * NH), 128, ATTN_SMEM_BYTES>>>(mask, out);
}

// round 7
// speedup vs baseline: 1.0819x; 1.0384x over previous
#include <cuda_runtime.h>
#include <cstdint>

#define BB 4
#define SS 2048
#define NH 16
#define HD 64
#define DM 1024

// Scratch for Q/K/V in [B, H, S, hd] layout (device globals: allocation-free).
__device__ __align__(16) float g_q[BB * NH * SS * HD];
__device__ __align__(16) float g_k[BB * NH * SS * HD];
__device__ __align__(16) float g_v[BB * NH * SS * HD];

__device__ __forceinline__ unsigned f2tf(float x) {
    unsigned u;
    asm("cvt.rna.tf32.f32 %0, %1;" : "=r"(u) : "f"(x));
    return u;
}

__device__ __forceinline__ void mma_tf32(float* c, const unsigned* a, const unsigned* b) {
    asm volatile(
        "mma.sync.aligned.m16n8k8.row.col.f32.tf32.tf32.f32 "
        "{%0,%1,%2,%3}, {%4,%5,%6,%7}, {%8,%9}, {%0,%1,%2,%3};"
        : "+f"(c[0]), "+f"(c[1]), "+f"(c[2]), "+f"(c[3])
        : "r"(a[0]), "r"(a[1]), "r"(a[2]), "r"(a[3]), "r"(b[0]), "r"(b[1]));
}

// ---------------------------------------------------------------------------
// Kernel 1: fused QKV projection with tf32 mma.sync (unchanged).
// ---------------------------------------------------------------------------
__global__ __launch_bounds__(256) void qkv_kernel(
    const float* __restrict__ x,
    const float* __restrict__ Wq, const float* __restrict__ bq,
    const float* __restrict__ Wk, const float* __restrict__ bk,
    const float* __restrict__ Wv, const float* __restrict__ bv)
{
    __shared__ unsigned As[128 * 36];
    __shared__ unsigned Bs[64 * 36];

    const int tid = threadIdx.x;
    const int lane = tid & 31;
    const int w = tid >> 5;
    const int wm = w & 3;
    const int wn = w >> 2;
    const int mRow0 = wm * 32;
    const int nCol0 = wn * 32;

    const int rowBase = blockIdx.y * 128;
    const int colBase = blockIdx.x * 64;
    const int mat = colBase / DM;
    const int colInMat = colBase % DM;
    const int head = colInMat / HD;

    const float* W    = (mat == 0) ? Wq : (mat == 1) ? Wk : Wv;
    const float* bias = (mat == 0) ? bq : (mat == 1) ? bk : bv;
    float*       dst  = (mat == 0) ? g_q : (mat == 1) ? g_k : g_v;

    float acc[2][4][4] = {};

    for (int kt = 0; kt < DM; kt += 32) {
        #pragma unroll
        for (int j = 0; j < 4; j++) {
            int idx = tid + j * 256;
            int row = idx >> 3;
            int c4 = (idx & 7) * 4;
            float4 a = *(const float4*)&x[(size_t)(rowBase + row) * DM + kt + c4];
            unsigned* p = &As[row * 36 + c4];
            p[0] = f2tf(a.x); p[1] = f2tf(a.y); p[2] = f2tf(a.z); p[3] = f2tf(a.w);
        }
        #pragma unroll
        for (int j = 0; j < 2; j++) {
            int idx = tid + j * 256;
            int row = idx >> 3;
            int c4 = (idx & 7) * 4;
            float4 bvv = *(const float4*)&W[(size_t)(colInMat + row) * DM + kt + c4];
            unsigned* p = &Bs[row * 36 + c4];
            p[0] = f2tf(bvv.x); p[1] = f2tf(bvv.y); p[2] = f2tf(bvv.z); p[3] = f2tf(bvv.w);
        }
        __syncthreads();

        #pragma unroll
        for (int kk = 0; kk < 4; kk++) {
            const int col = kk * 8 + (lane & 3);
            unsigned a[2][4];
            #pragma unroll
            for (int mi = 0; mi < 2; mi++) {
                int r = mRow0 + mi * 16 + (lane >> 2);
                a[mi][0] = As[r * 36 + col];
                a[mi][1] = As[(r + 8) * 36 + col];
                a[mi][2] = As[r * 36 + col + 4];
                a[mi][3] = As[(r + 8) * 36 + col + 4];
            }
            #pragma unroll
            for (int ni = 0; ni < 4; ni++) {
                int n0 = nCol0 + ni * 8 + (lane >> 2);
                unsigned b[2];
                b[0] = Bs[n0 * 36 + col];
                b[1] = Bs[n0 * 36 + col + 4];
                mma_tf32(acc[0][ni], a[0], b);
                mma_tf32(acc[1][ni], a[1], b);
            }
        }
        __syncthreads();
    }

    #pragma unroll
    for (int mi = 0; mi < 2; mi++) {
        #pragma unroll
        for (int ni = 0; ni < 4; ni++) {
            int d = nCol0 + ni * 8 + 2 * (lane & 3);
            float b0 = bias[colInMat + d];
            float b1 = bias[colInMat + d + 1];
            #pragma unroll
            for (int half = 0; half < 2; half++) {
                int token = rowBase + mRow0 + mi * 16 + (lane >> 2) + half * 8;
                int bidx = token >> 11;
                int s = token & (SS - 1);
                float2 o;
                o.x = acc[mi][ni][half * 2 + 0] + b0;
                o.y = acc[mi][ni][half * 2 + 1] + b1;
                *(float2*)&dst[(((size_t)(bidx * NH + head)) * SS + s) * HD + d] = o;
            }
        }
    }
}

// ---------------------------------------------------------------------------
// Kernel 2: attention, tf32 MMA, shuffle-free register P via k-permutation.
// PV contraction key-order is permuted (sigma(c)=2c / 2c+1) so the S
// accumulator registers are ALREADY in A-operand layout after relu^2:
//   pa = { p(s0), p(s2), p(s1), p(s3) }  (pure in-thread).
// V rows are stored at permuted slots rho(r)=(r>>1)|((r&1)<<2) within each
// 8-row group so B-frag reads keep the conflict-free (t, t+4) pattern.
// K buffer natural [key][d] stride 68; V stride 72. Double-buffered, 1 sync.
// ---------------------------------------------------------------------------
#define KSTR 68
#define VSTR 72
#define KWORDS (64 * KSTR)          // 4352
#define VWORDS (64 * VSTR)          // 4608
#define ATTN_SMEM_BYTES ((2 * KWORDS + 2 * VWORDS) * 4)   // 71680

__global__ __launch_bounds__(128, 3) void attn_kernel(
    const float* __restrict__ mask, float* __restrict__ out)
{
    extern __shared__ unsigned smem[];
    unsigned* kbuf[2] = { smem, smem + KWORDS };
    unsigned* vbuf[2] = { smem + 2 * KWORDS, smem + 2 * KWORDS + VWORDS };

    const int tid = threadIdx.x;
    const int lane = tid & 31;
    const int w = tid >> 5;
    const int qRow0 = w * 16;
    const int t = lane & 3;
    const int g = lane >> 2;

    const int bh = blockIdx.y;
    const int b = bh >> 4;
    const int h = bh & 15;
    const int qBase = blockIdx.x * 64;

    const float* qg = g_q + (size_t)bh * SS * HD;
    const float* kg = g_k + (size_t)bh * SS * HD;
    const float* vg = g_v + (size_t)bh * SS * HD;
    const float* maskrow = mask + b * SS;

    const float scale = 0.125f;

    // Hoist Q fragments (all 8 k-steps of d).
    unsigned a_q[8][4];
    {
        int r0 = qBase + qRow0 + g;
        int r1 = r0 + 8;
        #pragma unroll
        for (int kk = 0; kk < 8; kk++) {
            int col = kk * 8 + t;
            a_q[kk][0] = f2tf(qg[(size_t)r0 * HD + col]);
            a_q[kk][1] = f2tf(qg[(size_t)r1 * HD + col]);
            a_q[kk][2] = f2tf(qg[(size_t)r0 * HD + col + 4]);
            a_q[kk][3] = f2tf(qg[(size_t)r1 * HD + col + 4]);
        }
    }

    // Tile loaders: 64 keys x 64 dims, 128 threads, 8 float4 each.
    const int lrow = tid >> 4;            // 0..7 (+8j)
    const int lc4 = (tid & 15) * 4;       // 0..60

    float ctx[8][4] = {};

    // Preload tile 0 (V rows go to permuted slots).
    #pragma unroll
    for (int j = 0; j < 8; j++) {
        int row = lrow + j * 8;
        float4 kv = *(const float4*)&kg[(size_t)row * HD + lc4];
        uint4 ku;
        ku.x = f2tf(kv.x); ku.y = f2tf(kv.y); ku.z = f2tf(kv.z); ku.w = f2tf(kv.w);
        *(uint4*)&kbuf[0][row * KSTR + lc4] = ku;
        float4 vv = *(const float4*)&vg[(size_t)row * HD + lc4];
        uint4 vu;
        vu.x = f2tf(vv.x); vu.y = f2tf(vv.y); vu.z = f2tf(vv.z); vu.w = f2tf(vv.w);
        int vslot = (row & ~7) | ((row & 7) >> 1) | ((row & 1) << 2);
        *(uint4*)&vbuf[0][vslot * VSTR + lc4] = vu;
    }
    __syncthreads();

    for (int tt = 0; tt < 32; tt++) {
        const unsigned* kc = kbuf[tt & 1];
        const unsigned* vc = vbuf[tt & 1];
        unsigned* kn = kbuf[(tt + 1) & 1];
        unsigned* vn = vbuf[(tt + 1) & 1];
        const bool pf = (tt < 31);

        // Prefetch next K tile into registers (live through S phase only).
        float4 stg[8];
        if (pf) {
            const float* kt = kg + (size_t)((tt + 1) * 64) * HD;
            #pragma unroll
            for (int j = 0; j < 8; j++)
                stg[j] = *(const float4*)&kt[(size_t)(lrow + j * 8) * HD + lc4];
        }

        // --- S = Q K^T : warp covers 16 q x 64 keys ---
        float s[8][4] = {};
        #pragma unroll
        for (int kk = 0; kk < 8; kk++) {
            #pragma unroll
            for (int ni = 0; ni < 8; ni++) {
                const unsigned* kr = &kc[(ni * 8 + g) * KSTR + kk * 8 + t];
                unsigned bf[2] = { kr[0], kr[4] };
                mma_tf32(s[ni], a_q[kk], bf);
            }
        }

        // Retire K staging; start V staging (live through PV phase only).
        if (pf) {
            #pragma unroll
            for (int j = 0; j < 8; j++) {
                uint4 ku;
                ku.x = f2tf(stg[j].x); ku.y = f2tf(stg[j].y);
                ku.z = f2tf(stg[j].z); ku.w = f2tf(stg[j].w);
                *(uint4*)&kn[(lrow + j * 8) * KSTR + lc4] = ku;
            }
            const float* vt = vg + (size_t)((tt + 1) * 64) * HD;
            #pragma unroll
            for (int j = 0; j < 8; j++)
                stg[j] = *(const float4*)&vt[(size_t)(lrow + j * 8) * HD + lc4];
        }

        // --- P = relu(S*scale + mask)^2, in place, already A-layout ---
        unsigned pa[8][4];
        #pragma unroll
        for (int ni = 0; ni < 8; ni++) {
            float2 m2 = *(const float2*)&maskrow[tt * 64 + ni * 8 + 2 * t];
            float p0 = fmaxf(s[ni][0] * scale + m2.x, 0.0f);  // row g,   col 2t
            float p1 = fmaxf(s[ni][1] * scale + m2.y, 0.0f);  // row g,   col 2t+1
            float p2 = fmaxf(s[ni][2] * scale + m2.x, 0.0f);  // row g+8, col 2t
            float p3 = fmaxf(s[ni][3] * scale + m2.y, 0.0f);  // row g+8, col 2t+1
            pa[ni][0] = f2tf(p0 * p0);   // A k-col t    (= key 2t)
            pa[ni][1] = f2tf(p2 * p2);   // A row+8
            pa[ni][2] = f2tf(p1 * p1);   // A k-col t+4  (= key 2t+1)
            pa[ni][3] = f2tf(p3 * p3);
        }

        // --- ctx += P @ V : V slots already match permuted k-order ---
        #pragma unroll
        for (int kk = 0; kk < 8; kk++) {
            #pragma unroll
            for (int ti = 0; ti < 8; ti++) {
                unsigned bf[2];
                bf[0] = vc[(kk * 8 + t) * VSTR + ti * 8 + g];
                bf[1] = vc[(kk * 8 + t + 4) * VSTR + ti * 8 + g];
                mma_tf32(ctx[ti], pa[kk], bf);
            }
        }

        // Retire V staging (permuted slots).
        if (pf) {
            #pragma unroll
            for (int j = 0; j < 8; j++) {
                uint4 vu;
                vu.x = f2tf(stg[j].x); vu.y = f2tf(stg[j].y);
                vu.z = f2tf(stg[j].z); vu.w = f2tf(stg[j].w);
                int row = lrow + j * 8;
                int vslot = (row & ~7) | ((row & 7) >> 1) | ((row & 1) << 2);
                *(uint4*)&vn[vslot * VSTR + lc4] = vu;
            }
        }
        __syncthreads();
    }

    // Write context: out[b][s][h*64 + d].
    {
        int r0 = qBase + qRow0 + g;
        float* o0 = out + ((size_t)(b * SS + r0)) * DM + h * HD;
        float* o1 = o0 + (size_t)8 * DM;
        #pragma unroll
        for (int ti = 0; ti < 8; ti++) {
            int d = ti * 8 + 2 * t;
            *(float2*)&o0[d] = make_float2(ctx[ti][0], ctx[ti][1]);
            *(float2*)&o1[d] = make_float2(ctx[ti][2], ctx[ti][3]);
        }
    }
}

extern "C" void kernel_launch(void* const* d_in, const int* in_sizes, int n_in,
                              void* d_out, int out_size)
{
    const float* x    = (const float*)d_in[0];
    const float* mask = (const float*)d_in[1];
    const float* Wq   = (const float*)d_in[2];
    const float* bq   = (const float*)d_in[3];
    const float* Wk   = (const float*)d_in[4];
    const float* bk   = (const float*)d_in[5];
    const float* Wv   = (const float*)d_in[6];
    const float* bv   = (const float*)d_in[7];
    float* out = (float*)d_out;

    cudaFuncSetAttribute(attn_kernel,
                         cudaFuncAttributeMaxDynamicSharedMemorySize,
                         ATTN_SMEM_BYTES);

    qkv_kernel<<<dim3(3 * DM / 64, (BB * SS) / 128), 256>>>(
        x, Wq, bq, Wk, bk, Wv, bv);

    attn_kernel<<<dim3(SS / 64, BB * NH), 128, ATTN_SMEM_BYTES>>>(mask, out);
}

// round 8
// speedup vs baseline: 1.3024x; 1.2039x over previous
#include <cuda_runtime.h>
#include <cstdint>

#define BB 4
#define SS 2048
#define NH 16
#define HD 64
#define DM 1024

// Scratch for Q/K/V in [B, H, S, hd] layout (device globals: allocation-free).
__device__ __align__(16) float g_q[BB * NH * SS * HD];
__device__ __align__(16) float g_k[BB * NH * SS * HD];
__device__ __align__(16) float g_v[BB * NH * SS * HD];

__device__ __forceinline__ unsigned f2tf(float x) {
    unsigned u;
    asm("cvt.rna.tf32.f32 %0, %1;" : "=r"(u) : "f"(x));
    return u;
}

__device__ __forceinline__ void mma_tf32(float* c, const unsigned* a, const unsigned* b) {
    asm volatile(
        "mma.sync.aligned.m16n8k8.row.col.f32.tf32.tf32.f32 "
        "{%0,%1,%2,%3}, {%4,%5,%6,%7}, {%8,%9}, {%0,%1,%2,%3};"
        : "+f"(c[0]), "+f"(c[1]), "+f"(c[2]), "+f"(c[3])
        : "r"(a[0]), "r"(a[1]), "r"(a[2]), "r"(a[3]), "r"(b[0]), "r"(b[1]));
}

// ---------------------------------------------------------------------------
// Kernel 1: fused QKV projection with tf32 mma.sync (unchanged).
// ---------------------------------------------------------------------------
__global__ __launch_bounds__(256) void qkv_kernel(
    const float* __restrict__ x,
    const float* __restrict__ Wq, const float* __restrict__ bq,
    const float* __restrict__ Wk, const float* __restrict__ bk,
    const float* __restrict__ Wv, const float* __restrict__ bv)
{
    __shared__ unsigned As[128 * 36];
    __shared__ unsigned Bs[64 * 36];

    const int tid = threadIdx.x;
    const int lane = tid & 31;
    const int w = tid >> 5;
    const int wm = w & 3;
    const int wn = w >> 2;
    const int mRow0 = wm * 32;
    const int nCol0 = wn * 32;

    const int rowBase = blockIdx.y * 128;
    const int colBase = blockIdx.x * 64;
    const int mat = colBase / DM;
    const int colInMat = colBase % DM;
    const int head = colInMat / HD;

    const float* W    = (mat == 0) ? Wq : (mat == 1) ? Wk : Wv;
    const float* bias = (mat == 0) ? bq : (mat == 1) ? bk : bv;
    float*       dst  = (mat == 0) ? g_q : (mat == 1) ? g_k : g_v;

    float acc[2][4][4] = {};

    for (int kt = 0; kt < DM; kt += 32) {
        #pragma unroll
        for (int j = 0; j < 4; j++) {
            int idx = tid + j * 256;
            int row = idx >> 3;
            int c4 = (idx & 7) * 4;
            float4 a = *(const float4*)&x[(size_t)(rowBase + row) * DM + kt + c4];
            unsigned* p = &As[row * 36 + c4];
            p[0] = f2tf(a.x); p[1] = f2tf(a.y); p[2] = f2tf(a.z); p[3] = f2tf(a.w);
        }
        #pragma unroll
        for (int j = 0; j < 2; j++) {
            int idx = tid + j * 256;
            int row = idx >> 3;
            int c4 = (idx & 7) * 4;
            float4 bvv = *(const float4*)&W[(size_t)(colInMat + row) * DM + kt + c4];
            unsigned* p = &Bs[row * 36 + c4];
            p[0] = f2tf(bvv.x); p[1] = f2tf(bvv.y); p[2] = f2tf(bvv.z); p[3] = f2tf(bvv.w);
        }
        __syncthreads();

        #pragma unroll
        for (int kk = 0; kk < 4; kk++) {
            const int col = kk * 8 + (lane & 3);
            unsigned a[2][4];
            #pragma unroll
            for (int mi = 0; mi < 2; mi++) {
                int r = mRow0 + mi * 16 + (lane >> 2);
                a[mi][0] = As[r * 36 + col];
                a[mi][1] = As[(r + 8) * 36 + col];
                a[mi][2] = As[r * 36 + col + 4];
                a[mi][3] = As[(r + 8) * 36 + col + 4];
            }
            #pragma unroll
            for (int ni = 0; ni < 4; ni++) {
                int n0 = nCol0 + ni * 8 + (lane >> 2);
                unsigned b[2];
                b[0] = Bs[n0 * 36 + col];
                b[1] = Bs[n0 * 36 + col + 4];
                mma_tf32(acc[0][ni], a[0], b);
                mma_tf32(acc[1][ni], a[1], b);
            }
        }
        __syncthreads();
    }

    #pragma unroll
    for (int mi = 0; mi < 2; mi++) {
        #pragma unroll
        for (int ni = 0; ni < 4; ni++) {
            int d = nCol0 + ni * 8 + 2 * (lane & 3);
            float b0 = bias[colInMat + d];
            float b1 = bias[colInMat + d + 1];
            #pragma unroll
            for (int half = 0; half < 2; half++) {
                int token = rowBase + mRow0 + mi * 16 + (lane >> 2) + half * 8;
                int bidx = token >> 11;
                int s = token & (SS - 1);
                float2 o;
                o.x = acc[mi][ni][half * 2 + 0] + b0;
                o.y = acc[mi][ni][half * 2 + 1] + b1;
                *(float2*)&dst[(((size_t)(bidx * NH + head)) * SS + s) * HD + d] = o;
            }
        }
    }
}

// ---------------------------------------------------------------------------
// Kernel 2: attention, tf32 MMA, m=32 warp tiles, shuffle-free register P.
// Block: one (b,h), 128 q rows, 4 warps; warp = 32 q (2 m-frags) x 64 keys.
// Every B fragment feeds 2 MMAs -> LDS:MMA = 1:1.
// k-permutation (sigma(c)=2c/2c+1) keeps S accumulators in A-operand layout;
// V rows stored at slots rho(r)=(r>>1)|((r&1)<<2) within 8-row groups.
// K stride 68, V stride 72 (conflict-free). Double-buffered, 1 sync/tile.
// Split into 32-key halves to bound s/pa register pressure.
// ---------------------------------------------------------------------------
#define KSTR 68
#define VSTR 72
#define KWORDS (64 * KSTR)          // 4352
#define VWORDS (64 * VSTR)          // 4608
#define ATTN_SMEM_BYTES ((2 * KWORDS + 2 * VWORDS) * 4)   // 71680

__global__ __launch_bounds__(128, 2) void attn_kernel(
    const float* __restrict__ mask, float* __restrict__ out)
{
    extern __shared__ unsigned smem[];
    unsigned* kbuf[2] = { smem, smem + KWORDS };
    unsigned* vbuf[2] = { smem + 2 * KWORDS, smem + 2 * KWORDS + VWORDS };

    const int tid = threadIdx.x;
    const int lane = tid & 31;
    const int w = tid >> 5;
    const int qRow0 = w * 32;
    const int t = lane & 3;
    const int g = lane >> 2;

    const int bh = blockIdx.y;
    const int b = bh >> 4;
    const int h = bh & 15;
    const int qBase = blockIdx.x * 128;

    const float* qg = g_q + (size_t)bh * SS * HD;
    const float* kg = g_k + (size_t)bh * SS * HD;
    const float* vg = g_v + (size_t)bh * SS * HD;
    const float* maskrow = mask + b * SS;

    const float scale = 0.125f;

    // Hoist Q fragments: 2 m-frags x 8 k-steps.
    unsigned a_q[2][8][4];
    #pragma unroll
    for (int mi = 0; mi < 2; mi++) {
        int r0 = qBase + qRow0 + mi * 16 + g;
        int r1 = r0 + 8;
        #pragma unroll
        for (int kk = 0; kk < 8; kk++) {
            int col = kk * 8 + t;
            a_q[mi][kk][0] = f2tf(qg[(size_t)r0 * HD + col]);
            a_q[mi][kk][1] = f2tf(qg[(size_t)r1 * HD + col]);
            a_q[mi][kk][2] = f2tf(qg[(size_t)r0 * HD + col + 4]);
            a_q[mi][kk][3] = f2tf(qg[(size_t)r1 * HD + col + 4]);
        }
    }

    // Tile loaders: 64 keys x 64 dims, 128 threads, 8 float4 each.
    const int lrow = tid >> 4;            // 0..7 (+8j)
    const int lc4 = (tid & 15) * 4;       // 0..60

    float ctx[2][8][4] = {};

    // Preload tile 0 (V rows go to permuted slots).
    #pragma unroll
    for (int j = 0; j < 8; j++) {
        int row = lrow + j * 8;
        float4 kv = *(const float4*)&kg[(size_t)row * HD + lc4];
        uint4 ku;
        ku.x = f2tf(kv.x); ku.y = f2tf(kv.y); ku.z = f2tf(kv.z); ku.w = f2tf(kv.w);
        *(uint4*)&kbuf[0][row * KSTR + lc4] = ku;
        float4 vv = *(const float4*)&vg[(size_t)row * HD + lc4];
        uint4 vu;
        vu.x = f2tf(vv.x); vu.y = f2tf(vv.y); vu.z = f2tf(vv.z); vu.w = f2tf(vv.w);
        int vslot = (row & ~7) | ((row & 7) >> 1) | ((row & 1) << 2);
        *(uint4*)&vbuf[0][vslot * VSTR + lc4] = vu;
    }
    __syncthreads();

    for (int tt = 0; tt < 32; tt++) {
        const unsigned* kc = kbuf[tt & 1];
        const unsigned* vc = vbuf[tt & 1];
        unsigned* kn = kbuf[(tt + 1) & 1];
        unsigned* vn = vbuf[(tt + 1) & 1];
        const bool pf = (tt < 31);

        // Prefetch next K tile into registers (live through half 0 only).
        float4 stg[8];
        if (pf) {
            const float* kt = kg + (size_t)((tt + 1) * 64) * HD;
            #pragma unroll
            for (int j = 0; j < 8; j++)
                stg[j] = *(const float4*)&kt[(size_t)(lrow + j * 8) * HD + lc4];
        }

        // ---- HALF 0 : keys 0..31 ----
        {
            float s[2][4][4] = {};
            #pragma unroll
            for (int kk = 0; kk < 8; kk++) {
                #pragma unroll
                for (int ni = 0; ni < 4; ni++) {
                    const unsigned* kr = &kc[(ni * 8 + g) * KSTR + kk * 8 + t];
                    unsigned bf[2] = { kr[0], kr[4] };
                    mma_tf32(s[0][ni], a_q[0][kk], bf);
                    mma_tf32(s[1][ni], a_q[1][kk], bf);
                }
            }
            unsigned pa[2][4][4];
            #pragma unroll
            for (int ni = 0; ni < 4; ni++) {
                float2 m2 = *(const float2*)&maskrow[tt * 64 + ni * 8 + 2 * t];
                #pragma unroll
                for (int mi = 0; mi < 2; mi++) {
                    float p0 = fmaxf(s[mi][ni][0] * scale + m2.x, 0.0f);
                    float p1 = fmaxf(s[mi][ni][1] * scale + m2.y, 0.0f);
                    float p2 = fmaxf(s[mi][ni][2] * scale + m2.x, 0.0f);
                    float p3 = fmaxf(s[mi][ni][3] * scale + m2.y, 0.0f);
                    pa[mi][ni][0] = f2tf(p0 * p0);
                    pa[mi][ni][1] = f2tf(p2 * p2);
                    pa[mi][ni][2] = f2tf(p1 * p1);
                    pa[mi][ni][3] = f2tf(p3 * p3);
                }
            }
            #pragma unroll
            for (int kk = 0; kk < 4; kk++) {
                #pragma unroll
                for (int ti = 0; ti < 8; ti++) {
                    unsigned bf[2];
                    bf[0] = vc[(kk * 8 + t) * VSTR + ti * 8 + g];
                    bf[1] = vc[(kk * 8 + t + 4) * VSTR + ti * 8 + g];
                    mma_tf32(ctx[0][ti], pa[0][kk], bf);
                    mma_tf32(ctx[1][ti], pa[1][kk], bf);
                }
            }
        }

        // Retire K staging; start V staging (live through half 1 only).
        if (pf) {
            #pragma unroll
            for (int j = 0; j < 8; j++) {
                uint4 ku;
                ku.x = f2tf(stg[j].x); ku.y = f2tf(stg[j].y);
                ku.z = f2tf(stg[j].z); ku.w = f2tf(stg[j].w);
                *(uint4*)&kn[(lrow + j * 8) * KSTR + lc4] = ku;
            }
            const float* vt = vg + (size_t)((tt + 1) * 64) * HD;
            #pragma unroll
            for (int j = 0; j < 8; j++)
                stg[j] = *(const float4*)&vt[(size_t)(lrow + j * 8) * HD + lc4];
        }

        // ---- HALF 1 : keys 32..63 ----
        {
            float s[2][4][4] = {};
            #pragma unroll
            for (int kk = 0; kk < 8; kk++) {
                #pragma unroll
                for (int ni = 0; ni < 4; ni++) {
                    const unsigned* kr = &kc[((ni + 4) * 8 + g) * KSTR + kk * 8 + t];
                    unsigned bf[2] = { kr[0], kr[4] };
                    mma_tf32(s[0][ni], a_q[0][kk], bf);
                    mma_tf32(s[1][ni], a_q[1][kk], bf);
                }
            }
            unsigned pa[2][4][4];
            #pragma unroll
            for (int ni = 0; ni < 4; ni++) {
                float2 m2 = *(const float2*)&maskrow[tt * 64 + 32 + ni * 8 + 2 * t];
                #pragma unroll
                for (int mi = 0; mi < 2; mi++) {
                    float p0 = fmaxf(s[mi][ni][0] * scale + m2.x, 0.0f);
                    float p1 = fmaxf(s[mi][ni][1] * scale + m2.y, 0.0f);
                    float p2 = fmaxf(s[mi][ni][2] * scale + m2.x, 0.0f);
                    float p3 = fmaxf(s[mi][ni][3] * scale + m2.y, 0.0f);
                    pa[mi][ni][0] = f2tf(p0 * p0);
                    pa[mi][ni][1] = f2tf(p2 * p2);
                    pa[mi][ni][2] = f2tf(p1 * p1);
                    pa[mi][ni][3] = f2tf(p3 * p3);
                }
            }
            #pragma unroll
            for (int kk = 0; kk < 4; kk++) {
                #pragma unroll
                for (int ti = 0; ti < 8; ti++) {
                    unsigned bf[2];
                    bf[0] = vc[((kk + 4) * 8 + t) * VSTR + ti * 8 + g];
                    bf[1] = vc[((kk + 4) * 8 + t + 4) * VSTR + ti * 8 + g];
                    mma_tf32(ctx[0][ti], pa[0][kk], bf);
                    mma_tf32(ctx[1][ti], pa[1][kk], bf);
                }
            }
        }

        // Retire V staging (permuted slots).
        if (pf) {
            #pragma unroll
            for (int j = 0; j < 8; j++) {
                uint4 vu;
                vu.x = f2tf(stg[j].x); vu.y = f2tf(stg[j].y);
                vu.z = f2tf(stg[j].z); vu.w = f2tf(stg[j].w);
                int row = lrow + j * 8;
                int vslot = (row & ~7) | ((row & 7) >> 1) | ((row & 1) << 2);
                *(uint4*)&vn[vslot * VSTR + lc4] = vu;
            }
        }
        __syncthreads();
    }

    // Write context: out[b][s][h*64 + d].
    #pragma unroll
    for (int mi = 0; mi < 2; mi++) {
        int r0 = qBase + qRow0 + mi * 16 + g;
        float* o0 = out + ((size_t)(b * SS + r0)) * DM + h * HD;
        float* o1 = o0 + (size_t)8 * DM;
        #pragma unroll
        for (int ti = 0; ti < 8; ti++) {
            int d = ti * 8 + 2 * t;
            *(float2*)&o0[d] = make_float2(ctx[mi][ti][0], ctx[mi][ti][1]);
            *(float2*)&o1[d] = make_float2(ctx[mi][ti][2], ctx[mi][ti][3]);
        }
    }
}

extern "C" void kernel_launch(void* const* d_in, const int* in_sizes, int n_in,
                              void* d_out, int out_size)
{
    const float* x    = (const float*)d_in[0];
    const float* mask = (const float*)d_in[1];
    const float* Wq   = (const float*)d_in[2];
    const float* bq   = (const float*)d_in[3];
    const float* Wk   = (const float*)d_in[4];
    const float* bk   = (const float*)d_in[5];
    const float* Wv   = (const float*)d_in[6];
    const float* bv   = (const float*)d_in[7];
    float* out = (float*)d_out;

    cudaFuncSetAttribute(attn_kernel,
                         cudaFuncAttributeMaxDynamicSharedMemorySize,
                         ATTN_SMEM_BYTES);

    qkv_kernel<<<dim3(3 * DM / 64, (BB * SS) / 128), 256>>>(
        x, Wq, bq, Wk, bk, Wv, bv);

    attn_kernel<<<dim3(SS / 128, BB * NH), 128, ATTN_SMEM_BYTES>>>(mask, out);
}